// round 17
// baseline (speedup 1.0000x reference)
#include <cuda_runtime.h>
#include <math.h>

// Problem constants
#define BB 64
#define JJ 42
#define PP 16384
#define JG 6            // joint groups
#define JT 7            // joints per group (JG*JT == JJ)
#define PC 4            // P chunks
#define PPB (PP/PC)     // 4096 points per block
#define THREADS 256
#define PPT (PPB/THREADS)   // 16 points per thread
#define NWARP (THREADS/32)
#define GRID (BB*JG*PC)     // 1536 blocks
#define NBJ (BB*JJ)         // 2688

// Scratch: per-(b,j) partial min-squared-distance, one slot per P-chunk.
__device__ float g_partial[NBJ * PC];

// X-macro over the 7 joints: fully-scalar named variables (no arrays ->
// nothing for ptxas to demote to local memory).
#define FOR_J(X) X(0) X(1) X(2) X(3) X(4) X(5) X(6)

// No __launch_bounds__: live set ~57 scalars; default heuristic should pick
// <=64 regs -> 4 blocks/SM -> occ 50% (double the JT=14 variants).
__global__ void sdl_min_kernel(
    const float* __restrict__ pred,   // [B,J,3]
    const float* __restrict__ pts)    // [B,P,3]
{
    const int blk = blockIdx.x;
    const int pc = blk % PC;
    const int jg = (blk / PC) % JG;
    const int b  = blk / (PC * JG);
    const int t  = threadIdx.x;

    const float* jp = pred + (size_t)(b * JJ + jg * JT) * 3;

#define DECL(n) float mx##n, my##n, mz##n, acc##n;
    FOR_J(DECL)
#undef DECL

#define INIT(n) { float ax = jp[3*n+0], ay = jp[3*n+1], az = jp[3*n+2]; \
                  mx##n = -2.0f*ax; my##n = -2.0f*ay; mz##n = -2.0f*az; \
                  acc##n = 3.0e38f; }
    FOR_J(INIT)
#undef INIT

    // Points for this (b, pc): 4096 points via aligned float4 loads.
    // Data is L2-resident (12.6MB total) -> LDG ~ L2-hit latency; 8 warps/SMSP
    // at occ 50% hide it.
    const float4* p4 = (const float4*)(pts + ((size_t)b * PP + (size_t)pc * PPB) * 3);

#pragma unroll 1
    for (int it = 0; it < PPT / 4; it++) {
        const int f4 = it * (THREADS * 3) + t * 3;
        float4 A  = p4[f4 + 0];
        float4 Bv = p4[f4 + 1];
        float4 C  = p4[f4 + 2];

#pragma unroll
        for (int q = 0; q < 4; q++) {
            float px, py, pz;
            if (q == 0)      { px = A.x;  py = A.y;  pz = A.z;  }
            else if (q == 1) { px = A.w;  py = Bv.x; pz = Bv.y; }
            else if (q == 2) { px = Bv.z; py = Bv.w; pz = C.x;  }
            else             { px = C.y;  py = C.z;  pz = C.w;  }
            float b2 = fmaf(pz, pz, fmaf(py, py, px * px));
#define UPD(n) { float tq = fmaf(mx##n, px, fmaf(my##n, py, fmaf(mz##n, pz, b2))); \
                 acc##n = fminf(acc##n, tq); }
            FOR_J(UPD)
#undef UPD
        }
    }

    // Epilogue: fold |a|^2, warp min-reduce, deposit in smem per joint.
    __shared__ float smin[NWARP][JT];
    const int w = t >> 5, l = t & 31;

#define FIN(n) { float ax = jp[3*n+0], ay = jp[3*n+1], az = jp[3*n+2]; \
                 float v = acc##n + fmaf(az, az, fmaf(ay, ay, ax*ax)); \
                 v = fminf(v, __shfl_xor_sync(0xFFFFFFFFu, v, 16)); \
                 v = fminf(v, __shfl_xor_sync(0xFFFFFFFFu, v, 8));  \
                 v = fminf(v, __shfl_xor_sync(0xFFFFFFFFu, v, 4));  \
                 v = fminf(v, __shfl_xor_sync(0xFFFFFFFFu, v, 2));  \
                 v = fminf(v, __shfl_xor_sync(0xFFFFFFFFu, v, 1));  \
                 if (l == 0) smin[w][n] = v; }
    FOR_J(FIN)
#undef FIN

    __syncthreads();

    if (t < JT) {
        float v = smin[0][t];
#pragma unroll
        for (int wi = 1; wi < NWARP; wi++) v = fminf(v, smin[wi][t]);
        g_partial[(size_t)(b * JJ + jg * JT + t) * PC + pc] = v;
    }
}

// Finalize: single block, 1024 threads (R12's proven version).
__global__ __launch_bounds__(1024) void sdl_mse_kernel(
    const float* __restrict__ gt,   // [B,J]
    float* __restrict__ out)
{
    const int t = threadIdx.x;
    float s = 0.0f;
    const float4* gp = (const float4*)g_partial;
#pragma unroll
    for (int k = 0; k < 3; k++) {
        int i = t + k * 1024;
        if (i < NBJ) {
            float4 v = __ldcg(gp + i);
            float m = fminf(fminf(v.x, v.y), fminf(v.z, v.w));
            m = fmaxf(m, 0.0f);
            float d = sqrtf(m) - gt[i];
            s = fmaf(d, d, s);
        }
    }
    s += __shfl_xor_sync(0xFFFFFFFFu, s, 16);
    s += __shfl_xor_sync(0xFFFFFFFFu, s, 8);
    s += __shfl_xor_sync(0xFFFFFFFFu, s, 4);
    s += __shfl_xor_sync(0xFFFFFFFFu, s, 2);
    s += __shfl_xor_sync(0xFFFFFFFFu, s, 1);
    __shared__ float ssum[32];
    const int w = t >> 5, l = t & 31;
    if (l == 0) ssum[w] = s;
    __syncthreads();
    if (t == 0) {
        float tot = ssum[0];
#pragma unroll
        for (int wi = 1; wi < 32; wi++) tot += ssum[wi];
        out[0] = tot / (float)NBJ;
    }
}

extern "C" void kernel_launch(void* const* d_in, const int* in_sizes, int n_in,
                              void* d_out, int out_size) {
    (void)in_sizes; (void)n_in; (void)out_size;
    const float* pred = (const float*)d_in[0];   // [64,42,3]
    const float* pts  = (const float*)d_in[1];   // [64,16384,3]
    const float* gt   = (const float*)d_in[2];   // [64,42]
    float* out = (float*)d_out;

    sdl_min_kernel<<<GRID, THREADS>>>(pred, pts);
    sdl_mse_kernel<<<1, 1024>>>(gt, out);
}